// round 8
// baseline (speedup 1.0000x reference)
#include <cuda_runtime.h>
#include <cuda_bf16.h>
#include <cstdint>

// ---------------------------------------------------------------------------
// SPN neuron: B=32768, F=512, P=256 scope pairs, M=8 mixture components.
//
// Log2-domain quadratic form per (p,m):
//   t_m = A1*x1^2 + B1*x1 + A2*x2^2 + B2*x2 + C     (scaled by log2 e)
//   lse2 = mx + log2( sum_m 2^(t_m - mx) )
//   out[b] = ln(2) * sum_p lse2_p
//
// R7: revert to the measured-best main-loop config (grid 1184, occ 2 /
// 128 regs — R3's 37.3us), keep the fused prologue, and add a bank-aware
// pair->thread remap so each warp's 32 s0-gathers hit 32 distinct smem banks
// (the block result is a symmetric sum over pairs, so the assignment is free).
// ---------------------------------------------------------------------------

#define LOG2E_F    1.4426950408889634f
#define LN2_F      0.6931471805599453f
#define LOG2_2PI_F 2.6514961294723187f   // log2(2*pi)

constexpr int PF   = 512;   // features
constexpr int PP   = 256;   // scope pairs
constexpr int PM   = 8;     // mixture components
constexpr int ROWS = 8;     // batch rows per chunk

__device__ __forceinline__ float ex2f(float v) {
    float r; asm("ex2.approx.ftz.f32 %0, %1;" : "=f"(r) : "f"(v)); return r;
}
__device__ __forceinline__ float lg2f(float v) {
    float r; asm("lg2.approx.ftz.f32 %0, %1;" : "=f"(r) : "f"(v)); return r;
}
__device__ __forceinline__ void cp16(uint32_t smem_dst, const void* gmem_src) {
    asm volatile("cp.async.cg.shared.global [%0], [%1], 16;\n"
                 :: "r"(smem_dst), "l"(gmem_src));
}
__device__ __forceinline__ void cp_commit() {
    asm volatile("cp.async.commit_group;\n" ::: "memory");
}
template <int N>
__device__ __forceinline__ void cp_wait() {
    asm volatile("cp.async.wait_group %0;\n" :: "n"(N) : "memory");
}

// ---------------------------------------------------------------------------
// Single kernel. blockDim = 256: one scope pair per thread (after remap).
// ---------------------------------------------------------------------------
__global__ __launch_bounds__(256, 2)
void spn_main_kernel(const float* __restrict__ x,
                     const float* __restrict__ mean,
                     const float* __restrict__ stdv,
                     const float* __restrict__ wts,
                     const int*   __restrict__ w32,   // raw scopes as words
                     float* __restrict__ out,
                     int nchunks)
{
    __shared__ float sx[2][ROWS][PF];
    __shared__ float sred[8][ROWS];
    __shared__ int      s_cnt[32];
    __shared__ int      s_perm[PP];     // slot -> pair index
    __shared__ unsigned s_free[8];      // bitmask: 1 = slot free

    const int tid  = threadIdx.x;
    const int lane = tid & 31;
    const int warp = tid >> 5;

    const int stride = gridDim.x;
    const uint32_t sbase = (uint32_t)__cvta_generic_to_shared(&sx[0][0][0]);

    // ---- kick off first chunk's stage immediately (overlaps prologue) ----
    int c = blockIdx.x;
    if (c < nchunks) {
        const char* src = (const char*)(x + (size_t)c * ROWS * PF);
        #pragma unroll
        for (int k = 0; k < 4; k++)
            cp16(sbase + (tid + k * 256) * 16, src + (tid + k * 256) * 16);
    }
    cp_commit();

    // ---- scopes dtype detection (parallel, one barrier) ----
    // int64 LE values in [0,512): every odd 32-bit word of the first 512
    // words is zero. An int32 permutation of 0..511 has ~255 nonzero odd
    // words. Reads stay within the first 512 words -> safe for both dtypes.
    if (tid < 32) s_cnt[tid] = 0;
    if (tid < 8)  s_free[tid] = 0xffffffffu;
    const int any_odd = __syncthreads_or(w32[2 * tid + 1] != 0);

    // s0 of the pair this thread ORIGINALLY owns (pair index == tid)
    int s0_raw = (any_odd ? w32[2 * tid] : w32[4 * tid]) & (PF - 1);

    // ---- bank-aware remap: slot = rank*32 + (s0 & 31) ----
    // Non-overflow slots put exactly one s0-bank per lane position; the block
    // sum over pairs is permutation-invariant, so this is free.
    {
        int key  = s0_raw & 31;
        int rank = atomicAdd(&s_cnt[key], 1);
        int slot = rank * 32 + key;
        if (slot < PP) {
            s_perm[slot] = tid;
            atomicAnd(&s_free[slot >> 5], ~(1u << (slot & 31)));
        }
        __syncthreads();
        if (slot >= PP) {
            bool claimed = false;
            for (int w = 0; w < 8 && !claimed; w++) {
                while (!claimed) {
                    unsigned f = atomicOr(&s_free[w], 0u);
                    if (!f) break;
                    int b = __ffs(f) - 1;
                    unsigned m = 1u << b;
                    unsigned old = atomicAnd(&s_free[w], ~m);
                    if (old & m) { s_perm[w * 32 + b] = tid; claimed = true; }
                }
            }
        }
        __syncthreads();
    }
    const int p = s_perm[tid];   // pair handled by this thread

    int s0, s1;
    if (any_odd) { s0 = w32[2 * p]; s1 = w32[2 * p + 1]; }   // int32
    else         { s0 = w32[4 * p]; s1 = w32[4 * p + 2]; }   // int64
    s0 &= (PF - 1);  s1 &= (PF - 1);

    // ---- per-thread coefficient computation (log2 domain, prologue-only) ----
    float A1[PM], B1[PM], A2[PM], B2[PM], Cc[PM];
    {
        float w[PM], wsum = 0.f;
        #pragma unroll
        for (int m = 0; m < PM; m++) { w[m] = wts[p * PM + m]; wsum += w[m]; }
        const float l2wsum = lg2f(wsum);
        #pragma unroll
        for (int m = 0; m < PM; m++) {
            int base = (p * PM + m) * 2;
            float mu1 = mean[base + 0], mu2 = mean[base + 1];
            float sd1 = stdv[base + 0], sd2 = stdv[base + 1];
            float i1 = 1.f / (sd1 * sd1);
            float i2 = 1.f / (sd2 * sd2);
            A1[m] = -0.5f * i1 * LOG2E_F;
            B1[m] =  mu1  * i1 * LOG2E_F;
            A2[m] = -0.5f * i2 * LOG2E_F;
            B2[m] =  mu2  * i2 * LOG2E_F;
            Cc[m] = -0.5f * LOG2E_F * (mu1 * mu1 * i1 + mu2 * mu2 * i2)
                    - lg2f(sd1) - lg2f(sd2) - LOG2_2PI_F
                    + lg2f(w[m]) - l2wsum;
        }
    }

    // ---- main loop: double-buffered cp.async, scalar math ----
    int buf = 0;
    for (; c < nchunks; c += stride, buf ^= 1) {
        int cn = c + stride;
        if (cn < nchunks) {
            const char* src = (const char*)(x + (size_t)cn * ROWS * PF);
            uint32_t dst = sbase + (uint32_t)(buf ^ 1) * (ROWS * PF * 4);
            #pragma unroll
            for (int k = 0; k < 4; k++)
                cp16(dst + (tid + k * 256) * 16, src + (tid + k * 256) * 16);
        }
        cp_commit();
        cp_wait<1>();          // current chunk's group has landed
        __syncthreads();       // visible to all; prev iter's sred consumed

        float acc[ROWS];
        #pragma unroll
        for (int r = 0; r < ROWS; r++) {
            float x1 = sx[buf][r][s0];   // conflict-free: one bank per lane
            float x2 = sx[buf][r][s1];
            float x1s = x1 * x1;
            float x2s = x2 * x2;

            float t[PM];
            #pragma unroll
            for (int m = 0; m < PM; m++) {
                float v = fmaf(B2[m], x2, Cc[m]);
                v = fmaf(A2[m], x2s, v);
                v = fmaf(B1[m], x1, v);
                v = fmaf(A1[m], x1s, v);
                t[m] = v;
            }
            float m01 = fmaxf(t[0], t[1]), m23 = fmaxf(t[2], t[3]);
            float m45 = fmaxf(t[4], t[5]), m67 = fmaxf(t[6], t[7]);
            float mx  = fmaxf(fmaxf(m01, m23), fmaxf(m45, m67));
            #pragma unroll
            for (int m = 0; m < PM; m++) t[m] = ex2f(t[m] - mx);
            float s = ((t[0] + t[1]) + (t[2] + t[3]))
                    + ((t[4] + t[5]) + (t[6] + t[7]));
            acc[r] = mx + lg2f(s);
        }

        // Reduce 256 per-pair contributions -> 1 value per row
        #pragma unroll
        for (int r = 0; r < ROWS; r++) {
            float v = acc[r];
            #pragma unroll
            for (int off = 16; off; off >>= 1)
                v += __shfl_xor_sync(0xffffffffu, v, off);
            if (lane == 0) sred[warp][r] = v;
        }
        __syncthreads();

        if (tid < ROWS) {
            float s = 0.f;
            #pragma unroll
            for (int w = 0; w < 8; w++) s += sred[w][tid];
            out[c * ROWS + tid] = s * LN2_F;
        }
        // No trailing barrier: next iter's top barrier (after cp_wait) orders
        // this iter's sred reads against next iter's sred writes, and the
        // cp.async issued at next-iter top targets the buffer whose last
        // reads were sealed by this iteration's mid barrier.
    }
}

// ---------------------------------------------------------------------------
// Launch. Inputs: x f32[32768*512], mean f32[256*8*2], std f32[256*8*2],
// weights f32[256*8], scopes int{32,64}[512]. Output f32[32768].
// ---------------------------------------------------------------------------
extern "C" void kernel_launch(void* const* d_in, const int* in_sizes, int n_in,
                              void* d_out, int out_size)
{
    const float* x      = (const float*)d_in[0];
    const float* mean   = (const float*)d_in[1];
    const float* stdv   = (const float*)d_in[2];
    const float* wts    = (const float*)d_in[3];
    const int*   w32    = (const int*)d_in[4];
    float*       out    = (float*)d_out;

    const int B = in_sizes[0] / PF;          // 32768
    const int nchunks = B / ROWS;            // 4096

    // Grid 1184 (measured-best for the main loop in R3): ~3.5 chunks/block,
    // fine-grained tail balance, occ 2 at 128 regs.
    int blocks = 1184;
    if (blocks > nchunks) blocks = nchunks;
    spn_main_kernel<<<blocks, 256>>>(x, mean, stdv, wts, w32, out, nchunks);
}

// round 9
// speedup vs baseline: 1.5423x; 1.5423x over previous
#include <cuda_runtime.h>
#include <cuda_bf16.h>
#include <cstdint>

// ---------------------------------------------------------------------------
// SPN neuron: B=32768, F=512, P=256 scope pairs, M=8 mixture components.
//
// Log2-domain quadratic form per (p,m):
//   t_m = A1*x1^2 + B1*x1 + A2*x2^2 + B2*x2 + C     (scaled by log2 e)
//   lse2 = mx + log2( sum_m 2^(t_m - mx) )
//   out[b] = ln(2) * sum_p lse2_p
//
// R8: proven-best main loop (grid 1184, occ 2, register coefficients,
// double-buffered cp.async — 37.3us in R3) + a cheap parallel precompute
// kernel that (a) detects scopes dtype, (b) computes coefficients, and
// (c) computes a DETERMINISTIC bank-aware pair->slot permutation so each
// warp's 32 s0-gathers hit distinct smem banks. The block result is a
// symmetric sum over pairs, so the permutation is free. (R7 paid for this
// remap per-block with contended atomic spins: -35us. Here it's once.)
// ---------------------------------------------------------------------------

#define LOG2E_F    1.4426950408889634f
#define LN2_F      0.6931471805599453f
#define LOG2_2PI_F 2.6514961294723187f   // log2(2*pi)

constexpr int PF   = 512;   // features
constexpr int PP   = 256;   // scope pairs
constexpr int PM   = 8;     // mixture components
constexpr int ROWS = 8;     // batch rows per chunk

__device__ float g_coef[5 * PM * PP];   // [j in 0..4][m][slot], slot fastest
__device__ int2  g_scope2[PP];          // per-slot (s0, s1)

__device__ __forceinline__ float ex2f(float v) {
    float r; asm("ex2.approx.ftz.f32 %0, %1;" : "=f"(r) : "f"(v)); return r;
}
__device__ __forceinline__ float lg2f(float v) {
    float r; asm("lg2.approx.ftz.f32 %0, %1;" : "=f"(r) : "f"(v)); return r;
}
__device__ __forceinline__ void cp16(uint32_t smem_dst, const void* gmem_src) {
    asm volatile("cp.async.cg.shared.global [%0], [%1], 16;\n"
                 :: "r"(smem_dst), "l"(gmem_src));
}
__device__ __forceinline__ void cp_commit() {
    asm volatile("cp.async.commit_group;\n" ::: "memory");
}
template <int N>
__device__ __forceinline__ void cp_wait() {
    asm volatile("cp.async.wait_group %0;\n" :: "n"(N) : "memory");
}

// ---------------------------------------------------------------------------
// Precompute: 1 block, 256 threads. Thread == original pair index.
// Deterministic (scan-based, no atomics) bank-aware slot assignment.
// ---------------------------------------------------------------------------
__global__ void spn_precompute_kernel(const float* __restrict__ mean,
                                      const float* __restrict__ stdv,
                                      const float* __restrict__ wts,
                                      const int*   __restrict__ w32)
{
    __shared__ int keys[PP];
    __shared__ int ranks[PP];
    __shared__ int cnts[32];

    const int tid = threadIdx.x;

    // dtype detection: int64 LE values in [0,512) -> all odd words zero.
    const int any_odd = __syncthreads_or(w32[2 * tid + 1] != 0);
    int s0, s1;
    if (any_odd) { s0 = w32[2 * tid]; s1 = w32[2 * tid + 1]; }  // int32
    else         { s0 = w32[4 * tid]; s1 = w32[4 * tid + 2]; }  // int64
    s0 &= (PF - 1);  s1 &= (PF - 1);

    // ---- deterministic bank remap ----
    const int key = s0 & 31;
    keys[tid] = key;
    __syncthreads();
    int rank = 0;
    for (int j = 0; j < tid; j++) rank += (keys[j] == key);
    ranks[tid] = rank;
    if (tid < 32) {
        int c = 0;
        for (int j = 0; j < PP; j++) c += (keys[j] == tid);
        cnts[tid] = c;
    }
    __syncthreads();

    int my_slot;
    if (rank < 8) {
        my_slot = rank * 32 + key;
    } else {
        // overflow index = #(earlier overflow pairs)
        int oidx = 0;
        for (int j = 0; j < tid; j++) oidx += (ranks[j] >= 8);
        // free slot s (s = r*32+k) iff r >= min(cnts[k], 8); take the
        // oidx-th free slot in slot order. #free == #overflow.
        int cnt = 0; my_slot = PP - 1;
        for (int s = 0; s < PP; s++) {
            int k = s & 31, r = s >> 5;
            int filled = cnts[k] < 8 ? cnts[k] : 8;
            if (r >= filled) {
                if (cnt == oidx) { my_slot = s; break; }
                cnt++;
            }
        }
    }

    g_scope2[my_slot] = make_int2(s0, s1);

    // ---- coefficients for pair 'tid', stored at column 'my_slot' ----
    float w[PM], wsum = 0.f;
    #pragma unroll
    for (int m = 0; m < PM; m++) { w[m] = wts[tid * PM + m]; wsum += w[m]; }
    const float l2wsum = lg2f(wsum);
    #pragma unroll
    for (int m = 0; m < PM; m++) {
        int base = (tid * PM + m) * 2;
        float mu1 = mean[base + 0], mu2 = mean[base + 1];
        float sd1 = stdv[base + 0], sd2 = stdv[base + 1];
        float i1 = 1.f / (sd1 * sd1);
        float i2 = 1.f / (sd2 * sd2);
        g_coef[(0 * PM + m) * PP + my_slot] = -0.5f * i1 * LOG2E_F;
        g_coef[(1 * PM + m) * PP + my_slot] =  mu1  * i1 * LOG2E_F;
        g_coef[(2 * PM + m) * PP + my_slot] = -0.5f * i2 * LOG2E_F;
        g_coef[(3 * PM + m) * PP + my_slot] =  mu2  * i2 * LOG2E_F;
        g_coef[(4 * PM + m) * PP + my_slot] =
            -0.5f * LOG2E_F * (mu1 * mu1 * i1 + mu2 * mu2 * i2)
            - lg2f(sd1) - lg2f(sd2) - LOG2_2PI_F + lg2f(w[m]) - l2wsum;
    }
}

// ---------------------------------------------------------------------------
// Main kernel: blockDim = 256 (thread == slot). Persistent grid-stride over
// 8-row chunks, double-buffered cp.async staging. (R3's proven structure.)
// ---------------------------------------------------------------------------
__global__ __launch_bounds__(256, 2)
void spn_main_kernel(const float* __restrict__ x,
                     float* __restrict__ out,
                     int nchunks)
{
    __shared__ float sx[2][ROWS][PF];
    __shared__ float sred[8][ROWS];

    const int tid  = threadIdx.x;
    const int lane = tid & 31;
    const int warp = tid >> 5;

    // Coefficients -> registers (coalesced: slot is fastest dim of g_coef)
    float A1[PM], B1[PM], A2[PM], B2[PM], Cc[PM];
    #pragma unroll
    for (int m = 0; m < PM; m++) {
        A1[m] = g_coef[(0 * PM + m) * PP + tid];
        B1[m] = g_coef[(1 * PM + m) * PP + tid];
        A2[m] = g_coef[(2 * PM + m) * PP + tid];
        B2[m] = g_coef[(3 * PM + m) * PP + tid];
        Cc[m] = g_coef[(4 * PM + m) * PP + tid];
    }
    const int2 ss = g_scope2[tid];
    const int s0 = ss.x, s1 = ss.y;   // s0: one distinct bank per lane

    const int stride = gridDim.x;
    const uint32_t sbase = (uint32_t)__cvta_generic_to_shared(&sx[0][0][0]);

    // Prologue: stage first chunk into buffer 0.
    int c = blockIdx.x;
    if (c < nchunks) {
        const char* src = (const char*)(x + (size_t)c * ROWS * PF);
        #pragma unroll
        for (int k = 0; k < 4; k++)
            cp16(sbase + (tid + k * 256) * 16, src + (tid + k * 256) * 16);
    }
    cp_commit();

    int buf = 0;
    for (; c < nchunks; c += stride, buf ^= 1) {
        int cn = c + stride;
        if (cn < nchunks) {
            const char* src = (const char*)(x + (size_t)cn * ROWS * PF);
            uint32_t dst = sbase + (uint32_t)(buf ^ 1) * (ROWS * PF * 4);
            #pragma unroll
            for (int k = 0; k < 4; k++)
                cp16(dst + (tid + k * 256) * 16, src + (tid + k * 256) * 16);
        }
        cp_commit();
        cp_wait<1>();          // current chunk's group has landed
        __syncthreads();       // visible to all; prev iter's sred consumed

        float acc[ROWS];
        #pragma unroll
        for (int r = 0; r < ROWS; r++) {
            float x1 = sx[buf][r][s0];
            float x2 = sx[buf][r][s1];
            float x1s = x1 * x1;
            float x2s = x2 * x2;

            float t[PM];
            #pragma unroll
            for (int m = 0; m < PM; m++) {
                float v = fmaf(B2[m], x2, Cc[m]);
                v = fmaf(A2[m], x2s, v);
                v = fmaf(B1[m], x1, v);
                v = fmaf(A1[m], x1s, v);
                t[m] = v;
            }
            float m01 = fmaxf(t[0], t[1]), m23 = fmaxf(t[2], t[3]);
            float m45 = fmaxf(t[4], t[5]), m67 = fmaxf(t[6], t[7]);
            float mx  = fmaxf(fmaxf(m01, m23), fmaxf(m45, m67));
            #pragma unroll
            for (int m = 0; m < PM; m++) t[m] = ex2f(t[m] - mx);
            float s = ((t[0] + t[1]) + (t[2] + t[3]))
                    + ((t[4] + t[5]) + (t[6] + t[7]));
            acc[r] = mx + lg2f(s);
        }

        // Reduce 256 per-slot contributions -> 1 value per row
        #pragma unroll
        for (int r = 0; r < ROWS; r++) {
            float v = acc[r];
            #pragma unroll
            for (int off = 16; off; off >>= 1)
                v += __shfl_xor_sync(0xffffffffu, v, off);
            if (lane == 0) sred[warp][r] = v;
        }
        __syncthreads();

        if (tid < ROWS) {
            float s = 0.f;
            #pragma unroll
            for (int w = 0; w < 8; w++) s += sred[w][tid];
            out[c * ROWS + tid] = s * LN2_F;
        }
        // No trailing barrier: next iter's top barrier (after cp_wait) orders
        // this iter's sred reads against next iter's sred writes, and the
        // cp.async issued at next-iter top targets the buffer whose last
        // reads were sealed by this iteration's mid barrier.
    }
}

// ---------------------------------------------------------------------------
// Launch. Inputs: x f32[32768*512], mean f32[256*8*2], std f32[256*8*2],
// weights f32[256*8], scopes int{32,64}[512]. Output f32[32768].
// ---------------------------------------------------------------------------
extern "C" void kernel_launch(void* const* d_in, const int* in_sizes, int n_in,
                              void* d_out, int out_size)
{
    const float* x      = (const float*)d_in[0];
    const float* mean   = (const float*)d_in[1];
    const float* stdv   = (const float*)d_in[2];
    const float* wts    = (const float*)d_in[3];
    const int*   w32    = (const int*)d_in[4];
    float*       out    = (float*)d_out;

    const int B = in_sizes[0] / PF;          // 32768
    const int nchunks = B / ROWS;            // 4096

    spn_precompute_kernel<<<1, 256>>>(mean, stdv, wts, w32);

    // Grid 1184 (measured-best main-loop config, R3: 37.3us).
    int blocks = 1184;
    if (blocks > nchunks) blocks = nchunks;
    spn_main_kernel<<<blocks, 256>>>(x, out, nchunks);
}